// round 13
// baseline (speedup 1.0000x reference)
#include <cuda_runtime.h>
#include <cuda_fp16.h>
#include <math.h>
#include <stdint.h>

#define HH 188
#define WW 188
#define HW (188*188)
#define BB 4
#define MM 200
#define NMAX 500
#define SLAB_H 190
#define SLAB_W 194

#define OFF_HEAD 0
#define OFF_HM   (4*12*HW)
#define OFF_TB   (OFF_HM + 4*3*HW)
#define OFF_IND  (OFF_TB + 4*NMAX*8)
#define OFF_MASK (OFF_IND + 4*NMAX)
#define OUT_TOTAL (OFF_MASK + 4*NMAX)

// -------- static scratch (allocation-free; zero-initialized at load) --------
__device__ __align__(16) __half g_xh[(size_t)BB*SLAB_H*SLAB_W*512]; // acts fp16, halo stays 0
__device__ __align__(16) __half g_sh[(size_t)BB*SLAB_H*SLAB_W*64];  // stage1 out, halo stays 0
__device__ __align__(16) __half g_w0[9*8*64*64];    // [tap][cch][oc][ic]
__device__ __align__(16) __half g_w1[6*9*64*64];    // [head*9+tap][oc][ic]
__device__ __align__(16) __half g_h[(size_t)24*64*HW];  // hidden fp16 NCHW

// -------- mma.sync fp16 (sm_80+ baseline; tensor pipe on sm_100) --------
__device__ __forceinline__ void mma16816(float* d, const uint32_t* a,
                                         uint32_t b0, uint32_t b1) {
    asm volatile(
        "mma.sync.aligned.m16n8k16.row.col.f32.f16.f16.f32 "
        "{%0,%1,%2,%3}, {%4,%5,%6,%7}, {%8,%9}, {%0,%1,%2,%3};"
        : "+f"(d[0]), "+f"(d[1]), "+f"(d[2]), "+f"(d[3])
        : "r"(a[0]), "r"(a[1]), "r"(a[2]), "r"(a[3]), "r"(b0), "r"(b1));
}

// -------- conversion kernels --------
__global__ void convert_x(const float* __restrict__ sf)
{
    const int lane = threadIdx.x & 31;
    const int icg  = threadIdx.x >> 5;
    const int ix   = blockIdx.x * 32 + lane;
    const int iy   = blockIdx.y;
    const int b    = blockIdx.z;
    if (ix >= SLAB_W) return;
    const int y = iy - 1, x = ix - 1;
    const bool inr = ((unsigned)y < HH) && ((unsigned)x < WW);
    const size_t outbase = (((size_t)b * SLAB_H + iy) * SLAB_W + ix) * 512;
    for (int g2 = 0; g2 < 8; ++g2) {
        const int ic0 = (g2 * 8 + icg) * 8;
        unsigned int ph[4];
#pragma unroll
        for (int j = 0; j < 4; ++j) {
            unsigned int hh2 = 0;
#pragma unroll
            for (int s = 0; s < 2; ++s) {
                const int ic = ic0 + j * 2 + s;
                float v = inr ? sf[((size_t)(b * 512 + ic)) * HW + (size_t)y * WW + x] : 0.f;
                hh2 |= ((unsigned int)__half_as_ushort(__float2half_rn(v))) << (16 * s);
            }
            ph[j] = hh2;
        }
        *(uint4*)&g_xh[outbase + ic0] = make_uint4(ph[0], ph[1], ph[2], ph[3]);
    }
}

__global__ void wtrans0(const float* __restrict__ w)  // [64 oc][512 ic][9]
{
    int e = blockIdx.x * 256 + threadIdx.x;
    if (e >= 9 * 8 * 64 * 64) return;
    const int ic  = e & 63;
    const int oc  = (e >> 6) & 63;
    const int cch = (e >> 12) & 7;
    const int k   = e >> 15;
    g_w0[e] = __float2half_rn(w[(((size_t)oc * 512 + cch * 64 + ic) * 9) + k]);
}

__global__ void wtrans1(const float* __restrict__ w)  // [6][64 oc][64 ic][9]
{
    int e = blockIdx.x * 256 + threadIdx.x;
    if (e >= 6 * 9 * 64 * 64) return;
    const int ic = e & 63;
    const int oc = (e >> 6) & 63;
    const int hk = e >> 12;          // head*9 + k
    const int k = hk % 9, head = hk / 9;
    g_w1[e] = __float2half_rn(w[(((size_t)(head * 64 + oc)) * 64 + ic) * 9 + k]);
}

// -------- HMMA conv: one output row (192 px) x 64 oc per CTA --------
// smem: B [194][72]fp16 @0 (27936->28224 pad), A [64][72] @28224 ; 37440 B
#define SM_B  0
#define SM_A  28224
#define SM_TOTAL 37440

template<int CIN, int STAGE>
__global__ __launch_bounds__(256, 2) void mconv(const float* __restrict__ bn)
{
    extern __shared__ char smem[];
    const int tid  = threadIdx.x;
    const int wid  = tid >> 5;
    const int lane = tid & 31;
    const int g    = lane >> 2;
    const int tig  = lane & 3;
    const int mgrp = wid & 1;        // oc group: 0 -> oc 0-31, 1 -> 32-63
    const int ngrp = wid >> 1;       // px group: 48 px each
    const int y    = blockIdx.x;
    const int b    = blockIdx.y;
    const int head = (STAGE == 2) ? blockIdx.z : 0;

    const __half* xin = (STAGE == 1) ? g_xh : g_sh;
    const float* bnp = bn + head * 256;

    float acc[2][6][4];
#pragma unroll
    for (int mi = 0; mi < 2; ++mi)
#pragma unroll
        for (int j = 0; j < 6; ++j)
#pragma unroll
            for (int c = 0; c < 4; ++c) acc[mi][j][c] = 0.f;

    const int NCH = CIN / 64;
#pragma unroll 1
    for (int cch = 0; cch < NCH; ++cch) {
#pragma unroll 1
        for (int ky = 0; ky < 3; ++ky) {
            __syncthreads();
            {   // B copy: 194 px rows x 64 ic fp16
                const size_t rowb = ((size_t)(b * SLAB_H + y + ky) * SLAB_W) * CIN + cch * 64;
                for (int q = tid; q < 194 * 8; q += 256) {
                    const int p = q >> 3, s = q & 7;
                    *(uint4*)(smem + SM_B + p * 144 + s * 16) =
                        *(const uint4*)(xin + rowb + (size_t)p * CIN + s * 8);
                }
            }
#pragma unroll 1
            for (int kx = 0; kx < 3; ++kx) {
                if (kx > 0) __syncthreads();
                {   // A copy: 64 oc x 64 ic fp16
                    const int tap = ky * 3 + kx;
                    const __half* ws = (STAGE == 1)
                        ? g_w0 + ((size_t)(tap * 8 + cch) << 12)
                        : g_w1 + ((size_t)(head * 9 + tap) << 12);
                    for (int q = tid; q < 512; q += 256) {
                        const int oc = q >> 3, s = q & 7;
                        *(uint4*)(smem + SM_A + oc * 144 + s * 16) =
                            *(const uint4*)(ws + oc * 64 + s * 8);
                    }
                }
                __syncthreads();

#pragma unroll
                for (int kk = 0; kk < 4; ++kk) {
                    const int koff = kk * 32 + tig * 4;   // bytes into 64-ic row
                    uint32_t a[2][4];
#pragma unroll
                    for (int mi = 0; mi < 2; ++mi) {
                        const int abase = (mgrp * 32 + mi * 16 + g) * 144 + koff;
                        a[mi][0] = *(const uint32_t*)(smem + SM_A + abase);
                        a[mi][1] = *(const uint32_t*)(smem + SM_A + abase + 8 * 144);
                        a[mi][2] = *(const uint32_t*)(smem + SM_A + abase + 16);
                        a[mi][3] = *(const uint32_t*)(smem + SM_A + abase + 8 * 144 + 16);
                    }
#pragma unroll
                    for (int j = 0; j < 6; ++j) {
                        const int px = ngrp * 48 + j * 8 + kx + g;
                        const int bbase = px * 144 + koff;
                        const uint32_t b0 = *(const uint32_t*)(smem + SM_B + bbase);
                        const uint32_t b1 = *(const uint32_t*)(smem + SM_B + bbase + 16);
                        mma16816(acc[0][j], a[0], b0, b1);
                        mma16816(acc[1][j], a[1], b0, b1);
                    }
                }
            }
        }
    }
    __syncthreads();

    // -------- epilogue: BN + ReLU --------
    if (STAGE == 1) {
        // stage to smem [192 px][64 oc] fp16, then vectorized global copy
        __half* SH = (__half*)(smem + SM_B);
#pragma unroll
        for (int mi = 0; mi < 2; ++mi) {
            const int oc0 = mgrp * 32 + mi * 16 + g;
#pragma unroll
            for (int rr = 0; rr < 2; ++rr) {
                const int oc = oc0 + rr * 8;
                const float scale = bnp[oc] * rsqrtf(bnp[192 + oc] + 1e-5f);
                const float mean = bnp[128 + oc], beta = bnp[64 + oc];
#pragma unroll
                for (int j = 0; j < 6; ++j) {
                    const int px0 = ngrp * 48 + j * 8 + 2 * tig;
#pragma unroll
                    for (int cc = 0; cc < 2; ++cc) {
                        const float v = fmaxf((acc[mi][j][rr * 2 + cc] - mean) * scale + beta, 0.f);
                        SH[(px0 + cc) * 64 + oc] = __float2half_rn(v);
                    }
                }
            }
        }
        __syncthreads();
        const size_t obase = ((size_t)(b * SLAB_H + y + 1) * SLAB_W + 1) * 64;
        for (int q = tid; q < 188 * 8; q += 256) {
            const int p = q >> 3, s = q & 7;
            *(uint4*)(g_sh + obase + (size_t)p * 64 + s * 8) =
                *(const uint4*)((char*)SH + p * 128 + s * 16);
        }
    } else {
        // fp16 NCHW for conv2
        __half* outp = g_h + (size_t)(head * 4 + b) * 64 * HW + (size_t)y * WW;
#pragma unroll
        for (int mi = 0; mi < 2; ++mi) {
            const int oc0 = mgrp * 32 + mi * 16 + g;
#pragma unroll
            for (int rr = 0; rr < 2; ++rr) {
                const int oc = oc0 + rr * 8;
                const float scale = bnp[oc] * rsqrtf(bnp[192 + oc] + 1e-5f);
                const float mean = bnp[128 + oc], beta = bnp[64 + oc];
#pragma unroll
                for (int j = 0; j < 6; ++j) {
                    const int px0 = ngrp * 48 + j * 8 + 2 * tig;
                    if (px0 < 188) {
                        const float v0 = fmaxf((acc[mi][j][rr * 2 + 0] - mean) * scale + beta, 0.f);
                        const float v1 = fmaxf((acc[mi][j][rr * 2 + 1] - mean) * scale + beta, 0.f);
                        *(__half2*)(outp + (size_t)oc * HW + px0) = __floats2half2_rn(v0, v1);
                    }
                }
            }
        }
    }
}

// -------- conv2 (64->3) fp32 compute, fp16 input --------
__global__ __launch_bounds__(128)
void conv2_kernel(const float* __restrict__ w2,
                  const float* __restrict__ b2,
                  float* __restrict__ out)
{
    const int z    = blockIdx.z;
    const int head = z >> 2;
    const int b    = z & 3;
    const __half* img = g_h + (size_t)z * 64 * HW;

    __shared__ float sW2[1728];
    __shared__ float sK[4][34][36];

    const int tid = threadIdx.x;
    for (int e = tid; e < 1728; e += 128)
        sW2[e] = w2[(size_t)head * 1728 + e];

    const int row = tid >> 2;
    const int seg = (tid & 3) << 3;
    const int ty0 = blockIdx.y * 32;
    const int tx0 = blockIdx.x * 32;

    float acc[3][8];
#pragma unroll
    for (int o = 0; o < 3; ++o)
#pragma unroll
        for (int j = 0; j < 8; ++j) acc[o][j] = 0.f;

#pragma unroll 1
    for (int ic0 = 0; ic0 < 64; ic0 += 4) {
        __syncthreads();
        for (int e = tid; e < 4 * 34 * 34; e += 128) {
            int ic = e / 1156;
            int r  = (e % 1156) / 34;
            int c  = e % 34;
            int gy = ty0 - 1 + r;
            int gx = tx0 - 1 + c;
            float v = 0.f;
            if ((unsigned)gy < HH && (unsigned)gx < WW)
                v = __half2float(img[(size_t)(ic0 + ic) * HW + gy * WW + gx]);
            sK[ic][r][c] = v;
        }
        __syncthreads();

#pragma unroll 1
        for (int ic = 0; ic < 4; ++ic) {
#pragma unroll
            for (int ky = 0; ky < 3; ++ky) {
                const float* rp = &sK[ic][row + ky][seg];
                float4 v0 = *(const float4*)rp;
                float4 v1 = *(const float4*)(rp + 4);
                float2 v2 = *(const float2*)(rp + 8);
                float rowv[10] = { v0.x, v0.y, v0.z, v0.w,
                                   v1.x, v1.y, v1.z, v1.w,
                                   v2.x, v2.y };
#pragma unroll
                for (int kx = 0; kx < 3; ++kx) {
                    const int wb = (ic0 + ic) * 9 + ky * 3 + kx;
                    const float w0 = sW2[wb];
                    const float w1 = sW2[576 + wb];
                    const float wv2 = sW2[1152 + wb];
#pragma unroll
                    for (int j = 0; j < 8; ++j) {
                        acc[0][j] = fmaf(w0,  rowv[kx + j], acc[0][j]);
                        acc[1][j] = fmaf(w1,  rowv[kx + j], acc[1][j]);
                        acc[2][j] = fmaf(wv2, rowv[kx + j], acc[2][j]);
                    }
                }
            }
        }
    }

    const int y = ty0 + row;
    if (y < HH) {
        const int offc[6] = {0, 2, 3, 6, 8, 9};
        const int nch[6]  = {2, 1, 3, 2, 1, 3};
        for (int o = 0; o < nch[head]; ++o) {
            const float bias = b2[head * 3 + o];
            float* orow = out + OFF_HEAD +
                ((size_t)b * 12 + offc[head] + o) * HW + (size_t)y * WW;
#pragma unroll
            for (int j = 0; j < 8; ++j) {
                const int x = tx0 + seg + j;
                if (x < WW) orow[x] = acc[o][j] + bias;
            }
        }
    }
}

// -------- tail + target assignment --------
__global__ void zero_tail_kernel(float* __restrict__ out)
{
    const int n = OUT_TOTAL - OFF_HM;
    int i = blockIdx.x * blockDim.x + threadIdx.x;
    if (i < n) out[OFF_HM + i] = 0.f;
}

__global__ void assign_kernel(const float* __restrict__ gt, float* __restrict__ out)
{
    const int t = blockIdx.x * blockDim.x + threadIdx.x;
    if (t >= BB * MM) return;
    const int b = t / MM;
    const int m = t % MM;
    const float* gb = gt + (size_t)(b * MM + m) * 8;

    const float x  = gb[0], y  = gb[1], zc = gb[2];
    const float dx = gb[3], dy = gb[4], dz = gb[5];
    const float hd = gb[6];
    const int   cls = (int)gb[7];

    const bool valid = (dx > 0.f) && (dy > 0.f);
    const float vf = valid ? 1.f : 0.f;

    float cx = (x + 75.2f) / 0.1f / 8.0f;
    cx = fminf(fmaxf(cx, 0.f), (float)WW - 0.5f);
    float cy = (y + 75.2f) / 0.1f / 8.0f;
    cy = fminf(fmaxf(cy, 0.f), (float)HH - 0.5f);
    const int cxi = (int)floorf(cx);
    const int cyi = (int)floorf(cy);

    const float dxp = dx / 0.1f / 8.0f;
    const float dyp = dy / 0.1f / 8.0f;

    const float ov = 0.1f;
    const float hgt = dxp, wdt = dyp;
    const float b1 = hgt + wdt;
    const float c1 = wdt * hgt * (1.f - ov) / (1.f + ov);
    const float sq1 = sqrtf(fmaxf(b1 * b1 - 4.f * c1, 0.f));
    const float r1 = (b1 + sq1) * 0.5f;
    const float b2v = 2.f * (hgt + wdt);
    const float c2 = (1.f - ov) * wdt * hgt;
    const float sq2 = sqrtf(fmaxf(b2v * b2v - 16.f * c2, 0.f));
    const float r2 = (b2v + sq2) * 0.5f;
    const float a3 = 4.f * ov;
    const float b3 = -2.f * ov * (hgt + wdt);
    const float c3 = (ov - 1.f) * wdt * hgt;
    const float sq3 = sqrtf(fmaxf(b3 * b3 - 4.f * a3 * c3, 0.f));
    const float r3 = (b3 + sq3) * 0.5f;

    float r = fminf(fminf(r1, r2), r3);
    r = fmaxf(floorf(r), 2.0f);
    const float sigma = (2.f * r + 1.f) / 6.f;
    const float inv2s2 = 1.f / (2.f * sigma * sigma);

    float* tb = out + OFF_TB + (size_t)(b * NMAX + m) * 8;
    tb[0] = (cx - (float)cxi) * vf;
    tb[1] = (cy - (float)cyi) * vf;
    tb[2] = zc * vf;
    tb[3] = logf(dx) * vf;
    tb[4] = logf(dy) * vf;
    tb[5] = logf(dz) * vf;
    tb[6] = cosf(hd) * vf;
    tb[7] = sinf(hd) * vf;
    out[OFF_IND + b * NMAX + m]  = (float)((cyi * WW + cxi) * (valid ? 1 : 0));
    out[OFF_MASK + b * NMAX + m] = vf;

    if (!valid || cls < 1 || cls > 3) return;

    float* hm = out + OFF_HM + ((size_t)(b * 3 + (cls - 1))) * HW;
    const int ir = (int)r;
    for (int oy = -ir; oy <= ir; ++oy) {
        const int py = cyi + oy;
        if ((unsigned)py >= HH) continue;
        for (int ox = -ir; ox <= ir; ++ox) {
            const int px = cxi + ox;
            if ((unsigned)px >= WW) continue;
            const float g = expf(-(float)(oy * oy + ox * ox) * inv2s2);
            atomicMax((int*)&hm[(size_t)py * WW + px], __float_as_int(g));
        }
    }
}

// ---------------------------------------------------------------------------
extern "C" void kernel_launch(void* const* d_in, const int* in_sizes, int n_in,
                              void* d_out, int out_size)
{
    const float* sf       = (const float*)d_in[0];
    const float* gt       = (const float*)d_in[1];
    const float* w_shared = (const float*)d_in[2];
    const float* bn_sh    = (const float*)d_in[3];
    const float* w1       = (const float*)d_in[4];
    const float* bnh      = (const float*)d_in[5];
    const float* w2       = (const float*)d_in[6];
    const float* b2       = (const float*)d_in[7];
    float* out = (float*)d_out;

    (void)in_sizes; (void)n_in; (void)out_size;

    cudaFuncSetAttribute(mconv<512, 1>, cudaFuncAttributeMaxDynamicSharedMemorySize, SM_TOTAL);
    cudaFuncSetAttribute(mconv<64, 2>,  cudaFuncAttributeMaxDynamicSharedMemorySize, SM_TOTAL);

    {
        const int n = OUT_TOTAL - OFF_HM;
        zero_tail_kernel<<<(n + 255) / 256, 256>>>(out);
    }
    assign_kernel<<<(BB * MM + 255) / 256, 256>>>(gt, out);

    convert_x<<<dim3(7, SLAB_H, BB), 256>>>(sf);
    wtrans0<<<1152, 256>>>(w_shared);
    wtrans1<<<864, 256>>>(w1);

    // stage 1: 512 -> 64 (+BN+ReLU) -> fp16 slab
    mconv<512, 1><<<dim3(HH, BB), 256, SM_TOTAL>>>(bn_sh);
    // stage 2: 64 -> 64 (+BN+ReLU) x 6 heads -> fp16 NCHW hidden
    mconv<64, 2><<<dim3(HH, BB, 6), 256, SM_TOTAL>>>(bnh);
    // conv2: 64 -> 3 (+bias) with channel-select concat
    conv2_kernel<<<dim3(6, 6, 24), 128>>>(w2, b2, out);
}

// round 14
// speedup vs baseline: 1.0425x; 1.0425x over previous
#include <cuda_runtime.h>
#include <cuda_fp16.h>
#include <math.h>
#include <stdint.h>

#define HH 188
#define WW 188
#define HW (188*188)
#define BB 4
#define MM 200
#define NMAX 500
#define SLAB_H 190
#define SLAB_W 194

#define OFF_HEAD 0
#define OFF_HM   (4*12*HW)
#define OFF_TB   (OFF_HM + 4*3*HW)
#define OFF_IND  (OFF_TB + 4*NMAX*8)
#define OFF_MASK (OFF_IND + 4*NMAX)
#define OUT_TOTAL (OFF_MASK + 4*NMAX)

// -------- static scratch (allocation-free; zero-initialized at load) --------
__device__ __align__(16) __half g_xh[(size_t)BB*SLAB_H*SLAB_W*512]; // acts fp16, halo stays 0
__device__ __align__(16) __half g_sh[(size_t)BB*SLAB_H*SLAB_W*64];  // stage1 out, halo stays 0
__device__ __align__(16) __half g_w0[9*8*4096];     // packed frag layout [tap][cch][...]
__device__ __align__(16) __half g_w1[6*9*4096];     // packed frag layout [head*9+tap][...]
__device__ __align__(16) __half g_h[(size_t)24*64*HW];  // hidden fp16 NCHW

// -------- mma.sync fp16 (sm_80+ baseline; tensor pipe on sm_100) --------
__device__ __forceinline__ void mma16816(float* d, const uint32_t* a,
                                         uint32_t b0, uint32_t b1) {
    asm volatile(
        "mma.sync.aligned.m16n8k16.row.col.f32.f16.f16.f32 "
        "{%0,%1,%2,%3}, {%4,%5,%6,%7}, {%8,%9}, {%0,%1,%2,%3};"
        : "+f"(d[0]), "+f"(d[1]), "+f"(d[2]), "+f"(d[3])
        : "r"(a[0]), "r"(a[1]), "r"(a[2]), "r"(a[3]), "r"(b0), "r"(b1));
}

// -------- conversion kernels --------
__global__ void convert_x(const float* __restrict__ sf)
{
    const int lane = threadIdx.x & 31;
    const int icg  = threadIdx.x >> 5;
    const int ix   = blockIdx.x * 32 + lane;
    const int iy   = blockIdx.y;
    const int b    = blockIdx.z;
    if (ix >= SLAB_W) return;
    const int y = iy - 1, x = ix - 1;
    const bool inr = ((unsigned)y < HH) && ((unsigned)x < WW);
    const size_t outbase = (((size_t)b * SLAB_H + iy) * SLAB_W + ix) * 512;
    for (int g2 = 0; g2 < 8; ++g2) {
        const int ic0 = (g2 * 8 + icg) * 8;
        unsigned int ph[4];
#pragma unroll
        for (int j = 0; j < 4; ++j) {
            unsigned int hh2 = 0;
#pragma unroll
            for (int s = 0; s < 2; ++s) {
                const int ic = ic0 + j * 2 + s;
                float v = inr ? sf[((size_t)(b * 512 + ic)) * HW + (size_t)y * WW + x] : 0.f;
                hh2 |= ((unsigned int)__half_as_ushort(__float2half_rn(v))) << (16 * s);
            }
            ph[j] = hh2;
        }
        *(uint4*)&g_xh[outbase + ic0] = make_uint4(ph[0], ph[1], ph[2], ph[3]);
    }
}

// pack weights into per-thread mma fragment order:
// e = ((((tap*CCH+cch)*4+kk)*2+mgrp)*2+mi)*8+g)*4+tig)*8+h
// oc = mgrp*32+mi*16+g+((h>>1)&1)*8 ; ic = kk*16+tig*2+(h&1)+((h>>2)&1)*8
__global__ void wtrans0(const float* __restrict__ w)  // [64 oc][512 ic][9]
{
    int e = blockIdx.x * 256 + threadIdx.x;
    if (e >= 9 * 8 * 4096) return;
    const int h    = e & 7;
    const int tig  = (e >> 3) & 3;
    const int g    = (e >> 5) & 7;
    const int mi   = (e >> 8) & 1;
    const int mgrp = (e >> 9) & 1;
    const int kk   = (e >> 10) & 3;
    const int cch  = (e >> 12) & 7;
    const int tap  = e >> 15;
    const int oc = mgrp * 32 + mi * 16 + g + ((h >> 1) & 1) * 8;
    const int ic = kk * 16 + tig * 2 + (h & 1) + ((h >> 2) & 1) * 8;
    g_w0[e] = __float2half_rn(w[(((size_t)oc * 512) + cch * 64 + ic) * 9 + tap]);
}

__global__ void wtrans1(const float* __restrict__ w)  // [6][64 oc][64 ic][9]
{
    int e = blockIdx.x * 256 + threadIdx.x;
    if (e >= 6 * 9 * 4096) return;
    const int h    = e & 7;
    const int tig  = (e >> 3) & 3;
    const int g    = (e >> 5) & 7;
    const int mi   = (e >> 8) & 1;
    const int mgrp = (e >> 9) & 1;
    const int kk   = (e >> 10) & 3;
    const int hk   = e >> 12;         // head*9 + tap
    const int tap = hk % 9, head = hk / 9;
    const int oc = mgrp * 32 + mi * 16 + g + ((h >> 1) & 1) * 8;
    const int ic = kk * 16 + tig * 2 + (h & 1) + ((h >> 2) & 1) * 8;
    g_w1[e] = __float2half_rn(w[(((size_t)(head * 64 + oc)) * 64 + ic) * 9 + tap]);
}

// -------- HMMA conv: one output row (192 px) x 64 oc per CTA --------
// smem: B [194][144B] @0 (27936), A packed [3 kx][8192B] @27936 ; total 52512
#define SM_B  0
#define SM_A  27936
#define SM_TOTAL 52512

template<int CIN, int STAGE>
__global__ __launch_bounds__(256, 2) void mconv(const float* __restrict__ bn)
{
    extern __shared__ char smem[];
    const int tid  = threadIdx.x;
    const int wid  = tid >> 5;
    const int lane = tid & 31;
    const int g    = lane >> 2;
    const int tig  = lane & 3;
    const int mgrp = wid & 1;        // oc group: 0 -> oc 0-31, 1 -> 32-63
    const int ngrp = wid >> 1;       // px group: 48 px each
    const int y    = blockIdx.x;
    const int b    = blockIdx.y;
    const int head = (STAGE == 2) ? blockIdx.z : 0;

    const __half* xin = (STAGE == 1) ? g_xh : g_sh;
    const float* bnp = bn + head * 256;

    float acc[2][6][4];
#pragma unroll
    for (int mi = 0; mi < 2; ++mi)
#pragma unroll
        for (int j = 0; j < 6; ++j)
#pragma unroll
            for (int c = 0; c < 4; ++c) acc[mi][j][c] = 0.f;

    const int NCH = CIN / 64;
#pragma unroll 1
    for (int cch = 0; cch < NCH; ++cch) {
#pragma unroll 1
        for (int ky = 0; ky < 3; ++ky) {
            __syncthreads();
            {   // B copy: 194 px rows x 64 ic fp16
                const size_t rowb = ((size_t)(b * SLAB_H + y + ky) * SLAB_W) * CIN + cch * 64;
                for (int q = tid; q < 194 * 8; q += 256) {
                    const int p = q >> 3, s = q & 7;
                    *(uint4*)(smem + SM_B + p * 144 + s * 16) =
                        *(const uint4*)(xin + rowb + (size_t)p * CIN + s * 8);
                }
            }
            {   // A copy: all 3 kx taps, packed fragment layout (1536 uint4)
                const __half* ws = (STAGE == 1)
                    ? g_w0 + ((size_t)(ky * 3) * 8 + cch) * 4096
                    : g_w1 + ((size_t)(head * 9 + ky * 3)) * 4096;
                const size_t kxstride = (STAGE == 1) ? (8 * 4096) : 4096;
                for (int q = tid; q < 1536; q += 256) {
                    const int kxi = q >> 9;
                    const int r = q & 511;
                    *(uint4*)(smem + SM_A + kxi * 8192 + r * 16) =
                        *(const uint4*)(ws + kxi * kxstride + r * 8);
                }
            }
            __syncthreads();

#pragma unroll
            for (int kx = 0; kx < 3; ++kx) {
#pragma unroll
                for (int kk = 0; kk < 4; ++kk) {
                    const int koff = kk * 32 + tig * 4;   // bytes into B 64-ic row
                    uint32_t a[2][4];
#pragma unroll
                    for (int mi = 0; mi < 2; ++mi) {
                        const uint4 av = *(const uint4*)(smem + SM_A + kx * 8192 +
                            ((((kk * 2 + mgrp) * 2 + mi) * 32) + lane) * 16);
                        a[mi][0] = av.x; a[mi][1] = av.y; a[mi][2] = av.z; a[mi][3] = av.w;
                    }
#pragma unroll
                    for (int j = 0; j < 6; ++j) {
                        const int px = ngrp * 48 + j * 8 + kx + g;
                        const int bbase = px * 144 + koff;
                        const uint32_t b0 = *(const uint32_t*)(smem + SM_B + bbase);
                        const uint32_t b1 = *(const uint32_t*)(smem + SM_B + bbase + 16);
                        mma16816(acc[0][j], a[0], b0, b1);
                        mma16816(acc[1][j], a[1], b0, b1);
                    }
                }
            }
        }
    }
    __syncthreads();

    // -------- epilogue: BN + ReLU --------
    if (STAGE == 1) {
        // stage to smem [192 px][64 oc] fp16, then vectorized global copy
        __half* SH = (__half*)(smem + SM_B);
#pragma unroll
        for (int mi = 0; mi < 2; ++mi) {
            const int oc0 = mgrp * 32 + mi * 16 + g;
#pragma unroll
            for (int rr = 0; rr < 2; ++rr) {
                const int oc = oc0 + rr * 8;
                const float scale = bnp[oc] * rsqrtf(bnp[192 + oc] + 1e-5f);
                const float mean = bnp[128 + oc], beta = bnp[64 + oc];
#pragma unroll
                for (int j = 0; j < 6; ++j) {
                    const int px0 = ngrp * 48 + j * 8 + 2 * tig;
#pragma unroll
                    for (int cc = 0; cc < 2; ++cc) {
                        const float v = fmaxf((acc[mi][j][rr * 2 + cc] - mean) * scale + beta, 0.f);
                        SH[(px0 + cc) * 64 + oc] = __float2half_rn(v);
                    }
                }
            }
        }
        __syncthreads();
        const size_t obase = ((size_t)(b * SLAB_H + y + 1) * SLAB_W + 1) * 64;
        for (int q = tid; q < 188 * 8; q += 256) {
            const int p = q >> 3, s = q & 7;
            *(uint4*)(g_sh + obase + (size_t)p * 64 + s * 8) =
                *(const uint4*)((char*)SH + p * 128 + s * 16);
        }
    } else {
        // fp16 NCHW for conv2
        __half* outp = g_h + (size_t)(head * 4 + b) * 64 * HW + (size_t)y * WW;
#pragma unroll
        for (int mi = 0; mi < 2; ++mi) {
            const int oc0 = mgrp * 32 + mi * 16 + g;
#pragma unroll
            for (int rr = 0; rr < 2; ++rr) {
                const int oc = oc0 + rr * 8;
                const float scale = bnp[oc] * rsqrtf(bnp[192 + oc] + 1e-5f);
                const float mean = bnp[128 + oc], beta = bnp[64 + oc];
#pragma unroll
                for (int j = 0; j < 6; ++j) {
                    const int px0 = ngrp * 48 + j * 8 + 2 * tig;
                    if (px0 < 188) {
                        const float v0 = fmaxf((acc[mi][j][rr * 2 + 0] - mean) * scale + beta, 0.f);
                        const float v1 = fmaxf((acc[mi][j][rr * 2 + 1] - mean) * scale + beta, 0.f);
                        *(__half2*)(outp + (size_t)oc * HW + px0) = __floats2half2_rn(v0, v1);
                    }
                }
            }
        }
    }
}

// -------- conv2 (64->3) fp32 compute, fp16 input --------
__global__ __launch_bounds__(128)
void conv2_kernel(const float* __restrict__ w2,
                  const float* __restrict__ b2,
                  float* __restrict__ out)
{
    const int z    = blockIdx.z;
    const int head = z >> 2;
    const int b    = z & 3;
    const __half* img = g_h + (size_t)z * 64 * HW;

    __shared__ float sW2[1728];
    __shared__ float sK[4][34][36];

    const int tid = threadIdx.x;
    for (int e = tid; e < 1728; e += 128)
        sW2[e] = w2[(size_t)head * 1728 + e];

    const int row = tid >> 2;
    const int seg = (tid & 3) << 3;
    const int ty0 = blockIdx.y * 32;
    const int tx0 = blockIdx.x * 32;

    float acc[3][8];
#pragma unroll
    for (int o = 0; o < 3; ++o)
#pragma unroll
        for (int j = 0; j < 8; ++j) acc[o][j] = 0.f;

#pragma unroll 1
    for (int ic0 = 0; ic0 < 64; ic0 += 4) {
        __syncthreads();
        for (int e = tid; e < 4 * 34 * 34; e += 128) {
            int ic = e / 1156;
            int r  = (e % 1156) / 34;
            int c  = e % 34;
            int gy = ty0 - 1 + r;
            int gx = tx0 - 1 + c;
            float v = 0.f;
            if ((unsigned)gy < HH && (unsigned)gx < WW)
                v = __half2float(img[(size_t)(ic0 + ic) * HW + gy * WW + gx]);
            sK[ic][r][c] = v;
        }
        __syncthreads();

#pragma unroll 1
        for (int ic = 0; ic < 4; ++ic) {
#pragma unroll
            for (int ky = 0; ky < 3; ++ky) {
                const float* rp = &sK[ic][row + ky][seg];
                float4 v0 = *(const float4*)rp;
                float4 v1 = *(const float4*)(rp + 4);
                float2 v2 = *(const float2*)(rp + 8);
                float rowv[10] = { v0.x, v0.y, v0.z, v0.w,
                                   v1.x, v1.y, v1.z, v1.w,
                                   v2.x, v2.y };
#pragma unroll
                for (int kx = 0; kx < 3; ++kx) {
                    const int wb = (ic0 + ic) * 9 + ky * 3 + kx;
                    const float w0 = sW2[wb];
                    const float w1 = sW2[576 + wb];
                    const float wv2 = sW2[1152 + wb];
#pragma unroll
                    for (int j = 0; j < 8; ++j) {
                        acc[0][j] = fmaf(w0,  rowv[kx + j], acc[0][j]);
                        acc[1][j] = fmaf(w1,  rowv[kx + j], acc[1][j]);
                        acc[2][j] = fmaf(wv2, rowv[kx + j], acc[2][j]);
                    }
                }
            }
        }
    }

    const int y = ty0 + row;
    if (y < HH) {
        const int offc[6] = {0, 2, 3, 6, 8, 9};
        const int nch[6]  = {2, 1, 3, 2, 1, 3};
        for (int o = 0; o < nch[head]; ++o) {
            const float bias = b2[head * 3 + o];
            float* orow = out + OFF_HEAD +
                ((size_t)b * 12 + offc[head] + o) * HW + (size_t)y * WW;
#pragma unroll
            for (int j = 0; j < 8; ++j) {
                const int x = tx0 + seg + j;
                if (x < WW) orow[x] = acc[o][j] + bias;
            }
        }
    }
}

// -------- tail + target assignment --------
__global__ void zero_tail_kernel(float* __restrict__ out)
{
    const int n = OUT_TOTAL - OFF_HM;
    int i = blockIdx.x * blockDim.x + threadIdx.x;
    if (i < n) out[OFF_HM + i] = 0.f;
}

__global__ void assign_kernel(const float* __restrict__ gt, float* __restrict__ out)
{
    const int t = blockIdx.x * blockDim.x + threadIdx.x;
    if (t >= BB * MM) return;
    const int b = t / MM;
    const int m = t % MM;
    const float* gb = gt + (size_t)(b * MM + m) * 8;

    const float x  = gb[0], y  = gb[1], zc = gb[2];
    const float dx = gb[3], dy = gb[4], dz = gb[5];
    const float hd = gb[6];
    const int   cls = (int)gb[7];

    const bool valid = (dx > 0.f) && (dy > 0.f);
    const float vf = valid ? 1.f : 0.f;

    float cx = (x + 75.2f) / 0.1f / 8.0f;
    cx = fminf(fmaxf(cx, 0.f), (float)WW - 0.5f);
    float cy = (y + 75.2f) / 0.1f / 8.0f;
    cy = fminf(fmaxf(cy, 0.f), (float)HH - 0.5f);
    const int cxi = (int)floorf(cx);
    const int cyi = (int)floorf(cy);

    const float dxp = dx / 0.1f / 8.0f;
    const float dyp = dy / 0.1f / 8.0f;

    const float ov = 0.1f;
    const float hgt = dxp, wdt = dyp;
    const float b1 = hgt + wdt;
    const float c1 = wdt * hgt * (1.f - ov) / (1.f + ov);
    const float sq1 = sqrtf(fmaxf(b1 * b1 - 4.f * c1, 0.f));
    const float r1 = (b1 + sq1) * 0.5f;
    const float b2v = 2.f * (hgt + wdt);
    const float c2 = (1.f - ov) * wdt * hgt;
    const float sq2 = sqrtf(fmaxf(b2v * b2v - 16.f * c2, 0.f));
    const float r2 = (b2v + sq2) * 0.5f;
    const float a3 = 4.f * ov;
    const float b3 = -2.f * ov * (hgt + wdt);
    const float c3 = (ov - 1.f) * wdt * hgt;
    const float sq3 = sqrtf(fmaxf(b3 * b3 - 4.f * a3 * c3, 0.f));
    const float r3 = (b3 + sq3) * 0.5f;

    float r = fminf(fminf(r1, r2), r3);
    r = fmaxf(floorf(r), 2.0f);
    const float sigma = (2.f * r + 1.f) / 6.f;
    const float inv2s2 = 1.f / (2.f * sigma * sigma);

    float* tb = out + OFF_TB + (size_t)(b * NMAX + m) * 8;
    tb[0] = (cx - (float)cxi) * vf;
    tb[1] = (cy - (float)cyi) * vf;
    tb[2] = zc * vf;
    tb[3] = logf(dx) * vf;
    tb[4] = logf(dy) * vf;
    tb[5] = logf(dz) * vf;
    tb[6] = cosf(hd) * vf;
    tb[7] = sinf(hd) * vf;
    out[OFF_IND + b * NMAX + m]  = (float)((cyi * WW + cxi) * (valid ? 1 : 0));
    out[OFF_MASK + b * NMAX + m] = vf;

    if (!valid || cls < 1 || cls > 3) return;

    float* hm = out + OFF_HM + ((size_t)(b * 3 + (cls - 1))) * HW;
    const int ir = (int)r;
    for (int oy = -ir; oy <= ir; ++oy) {
        const int py = cyi + oy;
        if ((unsigned)py >= HH) continue;
        for (int ox = -ir; ox <= ir; ++ox) {
            const int px = cxi + ox;
            if ((unsigned)px >= WW) continue;
            const float g = expf(-(float)(oy * oy + ox * ox) * inv2s2);
            atomicMax((int*)&hm[(size_t)py * WW + px], __float_as_int(g));
        }
    }
}

// ---------------------------------------------------------------------------
extern "C" void kernel_launch(void* const* d_in, const int* in_sizes, int n_in,
                              void* d_out, int out_size)
{
    const float* sf       = (const float*)d_in[0];
    const float* gt       = (const float*)d_in[1];
    const float* w_shared = (const float*)d_in[2];
    const float* bn_sh    = (const float*)d_in[3];
    const float* w1       = (const float*)d_in[4];
    const float* bnh      = (const float*)d_in[5];
    const float* w2       = (const float*)d_in[6];
    const float* b2       = (const float*)d_in[7];
    float* out = (float*)d_out;

    (void)in_sizes; (void)n_in; (void)out_size;

    cudaFuncSetAttribute(mconv<512, 1>, cudaFuncAttributeMaxDynamicSharedMemorySize, SM_TOTAL);
    cudaFuncSetAttribute(mconv<64, 2>,  cudaFuncAttributeMaxDynamicSharedMemorySize, SM_TOTAL);

    // launch order puts mconv<512,1> at index 3 so ncu's skip window lands on it
    convert_x<<<dim3(7, SLAB_H, BB), 256>>>(sf);
    wtrans0<<<1152, 256>>>(w_shared);
    wtrans1<<<864, 256>>>(w1);

    // stage 1: 512 -> 64 (+BN+ReLU) -> fp16 slab
    mconv<512, 1><<<dim3(HH, BB), 256, SM_TOTAL>>>(bn_sh);
    // stage 2: 64 -> 64 (+BN+ReLU) x 6 heads -> fp16 NCHW hidden
    mconv<64, 2><<<dim3(HH, BB, 6), 256, SM_TOTAL>>>(bnh);
    // conv2: 64 -> 3 (+bias) with channel-select concat
    conv2_kernel<<<dim3(6, 6, 24), 128>>>(w2, b2, out);

    // independent tail work (zero then splat) moved after convs
    {
        const int n = OUT_TOTAL - OFF_HM;
        zero_tail_kernel<<<(n + 255) / 256, 256>>>(out);
    }
    assign_kernel<<<(BB * MM + 255) / 256, 256>>>(gt, out);
}

// round 15
// speedup vs baseline: 1.2922x; 1.2395x over previous
#include <cuda_runtime.h>
#include <cuda_fp16.h>
#include <math.h>
#include <stdint.h>

#define HH 188
#define WW 188
#define HW (188*188)
#define BB 4
#define MM 200
#define NMAX 500
#define SLAB_H 190
#define SLAB_W 194

#define OFF_HEAD 0
#define OFF_HM   (4*12*HW)
#define OFF_TB   (OFF_HM + 4*3*HW)
#define OFF_IND  (OFF_TB + 4*NMAX*8)
#define OFF_MASK (OFF_IND + 4*NMAX)
#define OUT_TOTAL (OFF_MASK + 4*NMAX)

// -------- static scratch (allocation-free; zero-initialized at load) --------
__device__ __align__(16) __half g_xh[(size_t)BB*SLAB_H*SLAB_W*512]; // acts fp16, halo stays 0
__device__ __align__(16) __half g_sh[(size_t)BB*SLAB_H*SLAB_W*64];  // stage1 out, halo stays 0
__device__ __align__(16) __half g_w0[9*8*4096];     // packed frag layout [tap][cch][...]
__device__ __align__(16) __half g_w1[6*9*4096];     // packed frag layout [head*9+tap][...]
__device__ __align__(16) __half g_h[(size_t)24*64*HW];  // hidden fp16 NCHW

// -------- mma.sync fp16 (sm_80+ baseline; tensor pipe on sm_100) --------
__device__ __forceinline__ void mma16816(float* d, const uint32_t* a,
                                         uint32_t b0, uint32_t b1) {
    asm volatile(
        "mma.sync.aligned.m16n8k16.row.col.f32.f16.f16.f32 "
        "{%0,%1,%2,%3}, {%4,%5,%6,%7}, {%8,%9}, {%0,%1,%2,%3};"
        : "+f"(d[0]), "+f"(d[1]), "+f"(d[2]), "+f"(d[3])
        : "r"(a[0]), "r"(a[1]), "r"(a[2]), "r"(a[3]), "r"(b0), "r"(b1));
}

// -------- conversion kernels --------
__global__ void convert_x(const float* __restrict__ sf)
{
    const int lane = threadIdx.x & 31;
    const int icg  = threadIdx.x >> 5;
    const int ix   = blockIdx.x * 32 + lane;
    const int iy   = blockIdx.y;
    const int b    = blockIdx.z;
    if (ix >= SLAB_W) return;
    const int y = iy - 1, x = ix - 1;
    const bool inr = ((unsigned)y < HH) && ((unsigned)x < WW);
    const size_t outbase = (((size_t)b * SLAB_H + iy) * SLAB_W + ix) * 512;
    for (int g2 = 0; g2 < 8; ++g2) {
        const int ic0 = (g2 * 8 + icg) * 8;
        unsigned int ph[4];
#pragma unroll
        for (int j = 0; j < 4; ++j) {
            unsigned int hh2 = 0;
#pragma unroll
            for (int s = 0; s < 2; ++s) {
                const int ic = ic0 + j * 2 + s;
                float v = inr ? sf[((size_t)(b * 512 + ic)) * HW + (size_t)y * WW + x] : 0.f;
                hh2 |= ((unsigned int)__half_as_ushort(__float2half_rn(v))) << (16 * s);
            }
            ph[j] = hh2;
        }
        *(uint4*)&g_xh[outbase + ic0] = make_uint4(ph[0], ph[1], ph[2], ph[3]);
    }
}

// pack weights into per-thread mma fragment order:
// oc = mgrp*32+mi*16+g+((h>>1)&1)*8 ; ic = kk*16+tig*2+(h&1)+((h>>2)&1)*8
__global__ void wtrans0(const float* __restrict__ w)  // [64 oc][512 ic][9]
{
    int e = blockIdx.x * 256 + threadIdx.x;
    if (e >= 9 * 8 * 4096) return;
    const int h    = e & 7;
    const int tig  = (e >> 3) & 3;
    const int g    = (e >> 5) & 7;
    const int mi   = (e >> 8) & 1;
    const int mgrp = (e >> 9) & 1;
    const int kk   = (e >> 10) & 3;
    const int cch  = (e >> 12) & 7;
    const int tap  = e >> 15;
    const int oc = mgrp * 32 + mi * 16 + g + ((h >> 1) & 1) * 8;
    const int ic = kk * 16 + tig * 2 + (h & 1) + ((h >> 2) & 1) * 8;
    g_w0[e] = __float2half_rn(w[(((size_t)oc * 512) + cch * 64 + ic) * 9 + tap]);
}

__global__ void wtrans1(const float* __restrict__ w)  // [6][64 oc][64 ic][9]
{
    int e = blockIdx.x * 256 + threadIdx.x;
    if (e >= 6 * 9 * 4096) return;
    const int h    = e & 7;
    const int tig  = (e >> 3) & 3;
    const int g    = (e >> 5) & 7;
    const int mi   = (e >> 8) & 1;
    const int mgrp = (e >> 9) & 1;
    const int kk   = (e >> 10) & 3;
    const int hk   = e >> 12;         // head*9 + tap
    const int tap = hk % 9, head = hk / 9;
    const int oc = mgrp * 32 + mi * 16 + g + ((h >> 1) & 1) * 8;
    const int ic = kk * 16 + tig * 2 + (h & 1) + ((h >> 2) & 1) * 8;
    g_w1[e] = __float2half_rn(w[(((size_t)(head * 64 + oc)) * 64 + ic) * 9 + tap]);
}

// -------- HMMA conv: one output row (192 px) x 64 oc per CTA --------
// smem: B only [194][144B] = 27936 (A loads straight from global, frag-packed)
#define SM_TOTAL 27936

template<int CIN, int STAGE>
__global__ __launch_bounds__(256, 2) void mconv(const float* __restrict__ bn)
{
    extern __shared__ char smem[];
    const int tid  = threadIdx.x;
    const int wid  = tid >> 5;
    const int lane = tid & 31;
    const int g    = lane >> 2;
    const int tig  = lane & 3;
    const int mgrp = wid & 1;        // oc group: 0 -> oc 0-31, 1 -> 32-63
    const int ngrp = wid >> 1;       // px group: 48 px each
    const int y    = blockIdx.x;
    const int b    = blockIdx.y;
    const int head = (STAGE == 2) ? blockIdx.z : 0;

    const __half* xin = (STAGE == 1) ? g_xh : g_sh;
    const float* bnp = bn + head * 256;

    float acc[2][6][4];
#pragma unroll
    for (int mi = 0; mi < 2; ++mi)
#pragma unroll
        for (int j = 0; j < 6; ++j)
#pragma unroll
            for (int c = 0; c < 4; ++c) acc[mi][j][c] = 0.f;

    const int NCH = CIN / 64;
    const int NIT = NCH * 3;

    uint4 rB[7];
    auto loadB = [&](int it) {
        const int cch = it / 3, ky = it % 3;
        const size_t rowb = ((size_t)(b * SLAB_H + y + ky) * SLAB_W) * CIN + cch * 64;
#pragma unroll
        for (int k = 0; k < 7; ++k) {
            const int q = tid + k * 256;
            if (q < 1552) {
                const int p = q >> 3, s = q & 7;
                rB[k] = *(const uint4*)(xin + rowb + (size_t)p * CIN + s * 8);
            }
        }
    };

    loadB(0);
#pragma unroll 1
    for (int it = 0; it < NIT; ++it) {
        __syncthreads();   // previous compute done; smem free
#pragma unroll
        for (int k = 0; k < 7; ++k) {
            const int q = tid + k * 256;
            if (q < 1552) {
                const int p = q >> 3, s = q & 7;
                *(uint4*)(smem + p * 144 + s * 16) = rB[k];
            }
        }
        __syncthreads();   // B(it) visible
        if (it + 1 < NIT) loadB(it + 1);   // prefetch; latency hidden by MMAs

        const int cch = it / 3, ky = it % 3;
        const __half* wA = (STAGE == 1)
            ? g_w0 + ((size_t)(ky * 3) * 8 + cch) * 4096
            : g_w1 + ((size_t)(head * 9 + ky * 3)) * 4096;
        const size_t kxstride = (STAGE == 1) ? (8 * 4096) : 4096;

#pragma unroll
        for (int kx = 0; kx < 3; ++kx) {
#pragma unroll
            for (int kk = 0; kk < 4; ++kk) {
                const int koff = kk * 32 + tig * 4;   // bytes into B 64-ic row
                uint32_t a[2][4];
#pragma unroll
                for (int mi = 0; mi < 2; ++mi) {
                    const uint4 av = *(const uint4*)(wA + kx * kxstride +
                        ((size_t)((((kk * 2 + mgrp) * 2 + mi) * 32) + lane)) * 8);
                    a[mi][0] = av.x; a[mi][1] = av.y; a[mi][2] = av.z; a[mi][3] = av.w;
                }
#pragma unroll
                for (int j = 0; j < 6; ++j) {
                    const int px = ngrp * 48 + j * 8 + kx + g;
                    const int bbase = px * 144 + koff;
                    const uint32_t b0 = *(const uint32_t*)(smem + bbase);
                    const uint32_t b1 = *(const uint32_t*)(smem + bbase + 16);
                    mma16816(acc[0][j], a[0], b0, b1);
                    mma16816(acc[1][j], a[1], b0, b1);
                }
            }
        }
    }
    __syncthreads();

    // -------- epilogue: BN + ReLU --------
    if (STAGE == 1) {
        // stage to smem [192 px][64 oc] fp16 (reuses B region), then global copy
        __half* SH = (__half*)smem;
#pragma unroll
        for (int mi = 0; mi < 2; ++mi) {
            const int oc0 = mgrp * 32 + mi * 16 + g;
#pragma unroll
            for (int rr = 0; rr < 2; ++rr) {
                const int oc = oc0 + rr * 8;
                const float scale = bnp[oc] * rsqrtf(bnp[192 + oc] + 1e-5f);
                const float mean = bnp[128 + oc], beta = bnp[64 + oc];
#pragma unroll
                for (int j = 0; j < 6; ++j) {
                    const int px0 = ngrp * 48 + j * 8 + 2 * tig;
#pragma unroll
                    for (int cc = 0; cc < 2; ++cc) {
                        const float v = fmaxf((acc[mi][j][rr * 2 + cc] - mean) * scale + beta, 0.f);
                        SH[(px0 + cc) * 64 + oc] = __float2half_rn(v);
                    }
                }
            }
        }
        __syncthreads();
        const size_t obase = ((size_t)(b * SLAB_H + y + 1) * SLAB_W + 1) * 64;
        for (int q = tid; q < 188 * 8; q += 256) {
            const int p = q >> 3, s = q & 7;
            *(uint4*)(g_sh + obase + (size_t)p * 64 + s * 8) =
                *(const uint4*)((char*)SH + p * 128 + s * 16);
        }
    } else {
        // fp16 NCHW for conv2
        __half* outp = g_h + (size_t)(head * 4 + b) * 64 * HW + (size_t)y * WW;
#pragma unroll
        for (int mi = 0; mi < 2; ++mi) {
            const int oc0 = mgrp * 32 + mi * 16 + g;
#pragma unroll
            for (int rr = 0; rr < 2; ++rr) {
                const int oc = oc0 + rr * 8;
                const float scale = bnp[oc] * rsqrtf(bnp[192 + oc] + 1e-5f);
                const float mean = bnp[128 + oc], beta = bnp[64 + oc];
#pragma unroll
                for (int j = 0; j < 6; ++j) {
                    const int px0 = ngrp * 48 + j * 8 + 2 * tig;
                    if (px0 < 188) {
                        const float v0 = fmaxf((acc[mi][j][rr * 2 + 0] - mean) * scale + beta, 0.f);
                        const float v1 = fmaxf((acc[mi][j][rr * 2 + 1] - mean) * scale + beta, 0.f);
                        *(__half2*)(outp + (size_t)oc * HW + px0) = __floats2half2_rn(v0, v1);
                    }
                }
            }
        }
    }
}

// -------- conv2 (64->3) fp32 compute, fp16 input --------
__global__ __launch_bounds__(128)
void conv2_kernel(const float* __restrict__ w2,
                  const float* __restrict__ b2,
                  float* __restrict__ out)
{
    const int z    = blockIdx.z;
    const int head = z >> 2;
    const int b    = z & 3;
    const __half* img = g_h + (size_t)z * 64 * HW;

    __shared__ float sW2[1728];
    __shared__ float sK[4][34][36];

    const int tid = threadIdx.x;
    for (int e = tid; e < 1728; e += 128)
        sW2[e] = w2[(size_t)head * 1728 + e];

    const int row = tid >> 2;
    const int seg = (tid & 3) << 3;
    const int ty0 = blockIdx.y * 32;
    const int tx0 = blockIdx.x * 32;

    float acc[3][8];
#pragma unroll
    for (int o = 0; o < 3; ++o)
#pragma unroll
        for (int j = 0; j < 8; ++j) acc[o][j] = 0.f;

#pragma unroll 1
    for (int ic0 = 0; ic0 < 64; ic0 += 4) {
        __syncthreads();
        for (int e = tid; e < 4 * 34 * 34; e += 128) {
            int ic = e / 1156;
            int r  = (e % 1156) / 34;
            int c  = e % 34;
            int gy = ty0 - 1 + r;
            int gx = tx0 - 1 + c;
            float v = 0.f;
            if ((unsigned)gy < HH && (unsigned)gx < WW)
                v = __half2float(img[(size_t)(ic0 + ic) * HW + gy * WW + gx]);
            sK[ic][r][c] = v;
        }
        __syncthreads();

#pragma unroll 1
        for (int ic = 0; ic < 4; ++ic) {
#pragma unroll
            for (int ky = 0; ky < 3; ++ky) {
                const float* rp = &sK[ic][row + ky][seg];
                float4 v0 = *(const float4*)rp;
                float4 v1 = *(const float4*)(rp + 4);
                float2 v2 = *(const float2*)(rp + 8);
                float rowv[10] = { v0.x, v0.y, v0.z, v0.w,
                                   v1.x, v1.y, v1.z, v1.w,
                                   v2.x, v2.y };
#pragma unroll
                for (int kx = 0; kx < 3; ++kx) {
                    const int wb = (ic0 + ic) * 9 + ky * 3 + kx;
                    const float w0 = sW2[wb];
                    const float w1 = sW2[576 + wb];
                    const float wv2 = sW2[1152 + wb];
#pragma unroll
                    for (int j = 0; j < 8; ++j) {
                        acc[0][j] = fmaf(w0,  rowv[kx + j], acc[0][j]);
                        acc[1][j] = fmaf(w1,  rowv[kx + j], acc[1][j]);
                        acc[2][j] = fmaf(wv2, rowv[kx + j], acc[2][j]);
                    }
                }
            }
        }
    }

    const int y = ty0 + row;
    if (y < HH) {
        const int offc[6] = {0, 2, 3, 6, 8, 9};
        const int nch[6]  = {2, 1, 3, 2, 1, 3};
        for (int o = 0; o < nch[head]; ++o) {
            const float bias = b2[head * 3 + o];
            float* orow = out + OFF_HEAD +
                ((size_t)b * 12 + offc[head] + o) * HW + (size_t)y * WW;
#pragma unroll
            for (int j = 0; j < 8; ++j) {
                const int x = tx0 + seg + j;
                if (x < WW) orow[x] = acc[o][j] + bias;
            }
        }
    }
}

// -------- tail + target assignment --------
__global__ void zero_tail_kernel(float* __restrict__ out)
{
    const int n = OUT_TOTAL - OFF_HM;
    int i = blockIdx.x * blockDim.x + threadIdx.x;
    if (i < n) out[OFF_HM + i] = 0.f;
}

__global__ void assign_kernel(const float* __restrict__ gt, float* __restrict__ out)
{
    const int t = blockIdx.x * blockDim.x + threadIdx.x;
    if (t >= BB * MM) return;
    const int b = t / MM;
    const int m = t % MM;
    const float* gb = gt + (size_t)(b * MM + m) * 8;

    const float x  = gb[0], y  = gb[1], zc = gb[2];
    const float dx = gb[3], dy = gb[4], dz = gb[5];
    const float hd = gb[6];
    const int   cls = (int)gb[7];

    const bool valid = (dx > 0.f) && (dy > 0.f);
    const float vf = valid ? 1.f : 0.f;

    float cx = (x + 75.2f) / 0.1f / 8.0f;
    cx = fminf(fmaxf(cx, 0.f), (float)WW - 0.5f);
    float cy = (y + 75.2f) / 0.1f / 8.0f;
    cy = fminf(fmaxf(cy, 0.f), (float)HH - 0.5f);
    const int cxi = (int)floorf(cx);
    const int cyi = (int)floorf(cy);

    const float dxp = dx / 0.1f / 8.0f;
    const float dyp = dy / 0.1f / 8.0f;

    const float ov = 0.1f;
    const float hgt = dxp, wdt = dyp;
    const float b1 = hgt + wdt;
    const float c1 = wdt * hgt * (1.f - ov) / (1.f + ov);
    const float sq1 = sqrtf(fmaxf(b1 * b1 - 4.f * c1, 0.f));
    const float r1 = (b1 + sq1) * 0.5f;
    const float b2v = 2.f * (hgt + wdt);
    const float c2 = (1.f - ov) * wdt * hgt;
    const float sq2 = sqrtf(fmaxf(b2v * b2v - 16.f * c2, 0.f));
    const float r2 = (b2v + sq2) * 0.5f;
    const float a3 = 4.f * ov;
    const float b3 = -2.f * ov * (hgt + wdt);
    const float c3 = (ov - 1.f) * wdt * hgt;
    const float sq3 = sqrtf(fmaxf(b3 * b3 - 4.f * a3 * c3, 0.f));
    const float r3 = (b3 + sq3) * 0.5f;

    float r = fminf(fminf(r1, r2), r3);
    r = fmaxf(floorf(r), 2.0f);
    const float sigma = (2.f * r + 1.f) / 6.f;
    const float inv2s2 = 1.f / (2.f * sigma * sigma);

    float* tb = out + OFF_TB + (size_t)(b * NMAX + m) * 8;
    tb[0] = (cx - (float)cxi) * vf;
    tb[1] = (cy - (float)cyi) * vf;
    tb[2] = zc * vf;
    tb[3] = logf(dx) * vf;
    tb[4] = logf(dy) * vf;
    tb[5] = logf(dz) * vf;
    tb[6] = cosf(hd) * vf;
    tb[7] = sinf(hd) * vf;
    out[OFF_IND + b * NMAX + m]  = (float)((cyi * WW + cxi) * (valid ? 1 : 0));
    out[OFF_MASK + b * NMAX + m] = vf;

    if (!valid || cls < 1 || cls > 3) return;

    float* hm = out + OFF_HM + ((size_t)(b * 3 + (cls - 1))) * HW;
    const int ir = (int)r;
    for (int oy = -ir; oy <= ir; ++oy) {
        const int py = cyi + oy;
        if ((unsigned)py >= HH) continue;
        for (int ox = -ir; ox <= ir; ++ox) {
            const int px = cxi + ox;
            if ((unsigned)px >= WW) continue;
            const float g = expf(-(float)(oy * oy + ox * ox) * inv2s2);
            atomicMax((int*)&hm[(size_t)py * WW + px], __float_as_int(g));
        }
    }
}

// ---------------------------------------------------------------------------
extern "C" void kernel_launch(void* const* d_in, const int* in_sizes, int n_in,
                              void* d_out, int out_size)
{
    const float* sf       = (const float*)d_in[0];
    const float* gt       = (const float*)d_in[1];
    const float* w_shared = (const float*)d_in[2];
    const float* bn_sh    = (const float*)d_in[3];
    const float* w1       = (const float*)d_in[4];
    const float* bnh      = (const float*)d_in[5];
    const float* w2       = (const float*)d_in[6];
    const float* b2       = (const float*)d_in[7];
    float* out = (float*)d_out;

    (void)in_sizes; (void)n_in; (void)out_size;

    // launch order keeps mconv<512,1> at index 3 for the ncu skip window
    convert_x<<<dim3(7, SLAB_H, BB), 256>>>(sf);
    wtrans0<<<1152, 256>>>(w_shared);
    wtrans1<<<864, 256>>>(w1);

    // stage 1: 512 -> 64 (+BN+ReLU) -> fp16 slab
    mconv<512, 1><<<dim3(HH, BB), 256, SM_TOTAL>>>(bn_sh);
    // stage 2: 64 -> 64 (+BN+ReLU) x 6 heads -> fp16 NCHW hidden
    mconv<64, 2><<<dim3(HH, BB, 6), 256, SM_TOTAL>>>(bnh);
    // conv2: 64 -> 3 (+bias) with channel-select concat
    conv2_kernel<<<dim3(6, 6, 24), 128>>>(w2, b2, out);

    // independent tail work (zero then splat) after convs
    {
        const int n = OUT_TOTAL - OFF_HM;
        zero_tail_kernel<<<(n + 255) / 256, 256>>>(out);
    }
    assign_kernel<<<(BB * MM + 255) / 256, 256>>>(gt, out);
}

// round 16
// speedup vs baseline: 1.3126x; 1.0158x over previous
#include <cuda_runtime.h>
#include <cuda_fp16.h>
#include <math.h>
#include <stdint.h>

#define HH 188
#define WW 188
#define HW (188*188)
#define BB 4
#define MM 200
#define NMAX 500
#define SLAB_H 190
#define SLAB_W 194

#define OFF_HEAD 0
#define OFF_HM   (4*12*HW)
#define OFF_TB   (OFF_HM + 4*3*HW)
#define OFF_IND  (OFF_TB + 4*NMAX*8)
#define OFF_MASK (OFF_IND + 4*NMAX)
#define OUT_TOTAL (OFF_MASK + 4*NMAX)

// -------- static scratch (allocation-free; zero-initialized at load) --------
__device__ __align__(16) __half g_xh[(size_t)BB*SLAB_H*SLAB_W*512]; // acts fp16, halo stays 0
__device__ __align__(16) __half g_sh[(size_t)BB*SLAB_H*SLAB_W*64];  // stage1 out, halo stays 0
__device__ __align__(16) __half g_w0[9*8*4096];     // packed frag layout [tap][cch][...]
__device__ __align__(16) __half g_w1[6*9*4096];     // packed frag layout [head*9+tap][...]
__device__ __align__(16) __half g_h[(size_t)24*64*HW];  // hidden fp16 NCHW

// -------- mma.sync fp16 (sm_80+ baseline; tensor pipe on sm_100) --------
__device__ __forceinline__ void mma16816(float* d, const uint32_t* a,
                                         uint32_t b0, uint32_t b1) {
    asm volatile(
        "mma.sync.aligned.m16n8k16.row.col.f32.f16.f16.f32 "
        "{%0,%1,%2,%3}, {%4,%5,%6,%7}, {%8,%9}, {%0,%1,%2,%3};"
        : "+f"(d[0]), "+f"(d[1]), "+f"(d[2]), "+f"(d[3])
        : "r"(a[0]), "r"(a[1]), "r"(a[2]), "r"(a[3]), "r"(b0), "r"(b1));
}

// -------- conversion kernels --------
__global__ void convert_x(const float* __restrict__ sf)
{
    const int lane = threadIdx.x & 31;
    const int icg  = threadIdx.x >> 5;
    const int ix   = blockIdx.x * 32 + lane;
    const int iy   = blockIdx.y;
    const int b    = blockIdx.z;
    if (ix >= SLAB_W) return;
    const int y = iy - 1, x = ix - 1;
    const bool inr = ((unsigned)y < HH) && ((unsigned)x < WW);
    const size_t outbase = (((size_t)b * SLAB_H + iy) * SLAB_W + ix) * 512;
    for (int g2 = 0; g2 < 8; ++g2) {
        const int ic0 = (g2 * 8 + icg) * 8;
        unsigned int ph[4];
#pragma unroll
        for (int j = 0; j < 4; ++j) {
            unsigned int hh2 = 0;
#pragma unroll
            for (int s = 0; s < 2; ++s) {
                const int ic = ic0 + j * 2 + s;
                float v = inr ? sf[((size_t)(b * 512 + ic)) * HW + (size_t)y * WW + x] : 0.f;
                hh2 |= ((unsigned int)__half_as_ushort(__float2half_rn(v))) << (16 * s);
            }
            ph[j] = hh2;
        }
        *(uint4*)&g_xh[outbase + ic0] = make_uint4(ph[0], ph[1], ph[2], ph[3]);
    }
}

// pack weights into per-thread mma fragment order:
// oc = mgrp*32+mi*16+g+((h>>1)&1)*8 ; ic = kk*16+tig*2+(h&1)+((h>>2)&1)*8
__global__ void wtrans0(const float* __restrict__ w)  // [64 oc][512 ic][9]
{
    int e = blockIdx.x * 256 + threadIdx.x;
    if (e >= 9 * 8 * 4096) return;
    const int h    = e & 7;
    const int tig  = (e >> 3) & 3;
    const int g    = (e >> 5) & 7;
    const int mi   = (e >> 8) & 1;
    const int mgrp = (e >> 9) & 1;
    const int kk   = (e >> 10) & 3;
    const int cch  = (e >> 12) & 7;
    const int tap  = e >> 15;
    const int oc = mgrp * 32 + mi * 16 + g + ((h >> 1) & 1) * 8;
    const int ic = kk * 16 + tig * 2 + (h & 1) + ((h >> 2) & 1) * 8;
    g_w0[e] = __float2half_rn(w[(((size_t)oc * 512) + cch * 64 + ic) * 9 + tap]);
}

__global__ void wtrans1(const float* __restrict__ w)  // [6][64 oc][64 ic][9]
{
    int e = blockIdx.x * 256 + threadIdx.x;
    if (e >= 6 * 9 * 4096) return;
    const int h    = e & 7;
    const int tig  = (e >> 3) & 3;
    const int g    = (e >> 5) & 7;
    const int mi   = (e >> 8) & 1;
    const int mgrp = (e >> 9) & 1;
    const int kk   = (e >> 10) & 3;
    const int hk   = e >> 12;         // head*9 + tap
    const int tap = hk % 9, head = hk / 9;
    const int oc = mgrp * 32 + mi * 16 + g + ((h >> 1) & 1) * 8;
    const int ic = kk * 16 + tig * 2 + (h & 1) + ((h >> 2) & 1) * 8;
    g_w1[e] = __float2half_rn(w[(((size_t)(head * 64 + oc)) * 64 + ic) * 9 + tap]);
}

// -------- stage 1 HMMA conv: one output row (192 px) x 64 oc per CTA --------
// smem: B only [194][144B] = 27936 (A loads straight from global, frag-packed)
#define SM1_TOTAL 27936

__global__ __launch_bounds__(256, 2) void mconv1(const float* __restrict__ bn)
{
    extern __shared__ char smem[];
    const int tid  = threadIdx.x;
    const int wid  = tid >> 5;
    const int lane = tid & 31;
    const int g    = lane >> 2;
    const int tig  = lane & 3;
    const int mgrp = wid & 1;
    const int ngrp = wid >> 1;
    const int y    = blockIdx.x;
    const int b    = blockIdx.y;
    const float* bnp = bn;

    float acc[2][6][4];
#pragma unroll
    for (int mi = 0; mi < 2; ++mi)
#pragma unroll
        for (int j = 0; j < 6; ++j)
#pragma unroll
            for (int c = 0; c < 4; ++c) acc[mi][j][c] = 0.f;

    const int NIT = 24;   // 8 cch x 3 ky

    uint4 rB[7];
    auto loadB = [&](int it) {
        const int cch = it / 3, ky = it % 3;
        const size_t rowb = ((size_t)(b * SLAB_H + y + ky) * SLAB_W) * 512 + cch * 64;
#pragma unroll
        for (int k = 0; k < 7; ++k) {
            const int q = tid + k * 256;
            if (q < 1552) {
                const int p = q >> 3, s = q & 7;
                rB[k] = *(const uint4*)(g_xh + rowb + (size_t)p * 512 + s * 8);
            }
        }
    };

    loadB(0);
#pragma unroll 1
    for (int it = 0; it < NIT; ++it) {
        __syncthreads();
#pragma unroll
        for (int k = 0; k < 7; ++k) {
            const int q = tid + k * 256;
            if (q < 1552) {
                const int p = q >> 3, s = q & 7;
                *(uint4*)(smem + p * 144 + s * 16) = rB[k];
            }
        }
        __syncthreads();
        if (it + 1 < NIT) loadB(it + 1);

        const int cch = it / 3, ky = it % 3;
        const __half* wA = g_w0 + ((size_t)(ky * 3) * 8 + cch) * 4096;

#pragma unroll
        for (int kx = 0; kx < 3; ++kx) {
#pragma unroll
            for (int kk = 0; kk < 4; ++kk) {
                const int koff = kk * 32 + tig * 4;
                uint32_t a[2][4];
#pragma unroll
                for (int mi = 0; mi < 2; ++mi) {
                    const uint4 av = *(const uint4*)(wA + (size_t)kx * 32768 +
                        ((size_t)((((kk * 2 + mgrp) * 2 + mi) * 32) + lane)) * 8);
                    a[mi][0] = av.x; a[mi][1] = av.y; a[mi][2] = av.z; a[mi][3] = av.w;
                }
#pragma unroll
                for (int j = 0; j < 6; ++j) {
                    const int px = ngrp * 48 + j * 8 + kx + g;
                    const int bbase = px * 144 + koff;
                    const uint32_t b0 = *(const uint32_t*)(smem + bbase);
                    const uint32_t b1 = *(const uint32_t*)(smem + bbase + 16);
                    mma16816(acc[0][j], a[0], b0, b1);
                    mma16816(acc[1][j], a[1], b0, b1);
                }
            }
        }
    }
    __syncthreads();

    // epilogue: BN+ReLU -> fp16 slab (stage to smem, vectorized global copy)
    __half* SH = (__half*)smem;
#pragma unroll
    for (int mi = 0; mi < 2; ++mi) {
        const int oc0 = mgrp * 32 + mi * 16 + g;
#pragma unroll
        for (int rr = 0; rr < 2; ++rr) {
            const int oc = oc0 + rr * 8;
            const float scale = bnp[oc] * rsqrtf(bnp[192 + oc] + 1e-5f);
            const float mean = bnp[128 + oc], beta = bnp[64 + oc];
#pragma unroll
            for (int j = 0; j < 6; ++j) {
                const int px0 = ngrp * 48 + j * 8 + 2 * tig;
#pragma unroll
                for (int cc = 0; cc < 2; ++cc) {
                    const float v = fmaxf((acc[mi][j][rr * 2 + cc] - mean) * scale + beta, 0.f);
                    SH[(px0 + cc) * 64 + oc] = __float2half_rn(v);
                }
            }
        }
    }
    __syncthreads();
    const size_t obase = ((size_t)(b * SLAB_H + y + 1) * SLAB_W + 1) * 64;
    for (int q = tid; q < 188 * 8; q += 256) {
        const int p = q >> 3, s = q & 7;
        *(uint4*)(g_sh + obase + (size_t)p * 64 + s * 8) =
            *(const uint4*)((char*)SH + p * 128 + s * 16);
    }
}

// -------- stage 2 multi-head: 3 ky B-slabs resident, 6 heads per CTA --------
// smem: 3 x [194][144B] = 83808
#define SM2_TOTAL (3 * 27936)

__global__ __launch_bounds__(256, 2) void mconv2_mh(const float* __restrict__ bn)
{
    extern __shared__ char smem[];
    const int tid  = threadIdx.x;
    const int wid  = tid >> 5;
    const int lane = tid & 31;
    const int g    = lane >> 2;
    const int tig  = lane & 3;
    const int mgrp = wid & 1;
    const int ngrp = wid >> 1;
    const int y    = blockIdx.x;
    const int b    = blockIdx.y;

    // one-time load of 3 ky slabs (64 ic each)
    for (int q = tid; q < 3 * 1552; q += 256) {
        const int ky = q / 1552, r = q % 1552;
        const int p = r >> 3, s = r & 7;
        const size_t rowb = ((size_t)(b * SLAB_H + y + ky) * SLAB_W) * 64;
        *(uint4*)(smem + ky * 27936 + p * 144 + s * 16) =
            *(const uint4*)(g_sh + rowb + (size_t)p * 64 + s * 8);
    }
    __syncthreads();

#pragma unroll 1
    for (int head = 0; head < 6; ++head) {
        float acc[2][6][4];
#pragma unroll
        for (int mi = 0; mi < 2; ++mi)
#pragma unroll
            for (int j = 0; j < 6; ++j)
#pragma unroll
                for (int c = 0; c < 4; ++c) acc[mi][j][c] = 0.f;

#pragma unroll 1
        for (int ky = 0; ky < 3; ++ky) {
            const char* Bb = smem + ky * 27936;
            const __half* wA = g_w1 + (size_t)(head * 9 + ky * 3) * 4096;
#pragma unroll
            for (int kx = 0; kx < 3; ++kx) {
#pragma unroll
                for (int kk = 0; kk < 4; ++kk) {
                    const int koff = kk * 32 + tig * 4;
                    uint32_t a[2][4];
#pragma unroll
                    for (int mi = 0; mi < 2; ++mi) {
                        const uint4 av = *(const uint4*)(wA + (size_t)kx * 4096 +
                            ((size_t)((((kk * 2 + mgrp) * 2 + mi) * 32) + lane)) * 8);
                        a[mi][0] = av.x; a[mi][1] = av.y; a[mi][2] = av.z; a[mi][3] = av.w;
                    }
#pragma unroll
                    for (int j = 0; j < 6; ++j) {
                        const int px = ngrp * 48 + j * 8 + kx + g;
                        const int bbase = px * 144 + koff;
                        const uint32_t b0 = *(const uint32_t*)(Bb + bbase);
                        const uint32_t b1 = *(const uint32_t*)(Bb + bbase + 16);
                        mma16816(acc[0][j], a[0], b0, b1);
                        mma16816(acc[1][j], a[1], b0, b1);
                    }
                }
            }
        }

        // per-head epilogue: BN+ReLU -> fp16 NCHW hidden (no syncs needed)
        const float* bnp = bn + head * 256;
        __half* outp = g_h + (size_t)(head * 4 + b) * 64 * HW + (size_t)y * WW;
#pragma unroll
        for (int mi = 0; mi < 2; ++mi) {
            const int oc0 = mgrp * 32 + mi * 16 + g;
#pragma unroll
            for (int rr = 0; rr < 2; ++rr) {
                const int oc = oc0 + rr * 8;
                const float scale = bnp[oc] * rsqrtf(bnp[192 + oc] + 1e-5f);
                const float mean = bnp[128 + oc], beta = bnp[64 + oc];
#pragma unroll
                for (int j = 0; j < 6; ++j) {
                    const int px0 = ngrp * 48 + j * 8 + 2 * tig;
                    if (px0 < 188) {
                        const float v0 = fmaxf((acc[mi][j][rr * 2 + 0] - mean) * scale + beta, 0.f);
                        const float v1 = fmaxf((acc[mi][j][rr * 2 + 1] - mean) * scale + beta, 0.f);
                        *(__half2*)(outp + (size_t)oc * HW + px0) = __floats2half2_rn(v0, v1);
                    }
                }
            }
        }
    }
}

// -------- conv2 (64->3) fp32 compute, fp16 input --------
__global__ __launch_bounds__(128)
void conv2_kernel(const float* __restrict__ w2,
                  const float* __restrict__ b2,
                  float* __restrict__ out)
{
    const int z    = blockIdx.z;
    const int head = z >> 2;
    const int b    = z & 3;
    const __half* img = g_h + (size_t)z * 64 * HW;

    __shared__ float sW2[1728];
    __shared__ float sK[4][34][36];

    const int tid = threadIdx.x;
    for (int e = tid; e < 1728; e += 128)
        sW2[e] = w2[(size_t)head * 1728 + e];

    const int row = tid >> 2;
    const int seg = (tid & 3) << 3;
    const int ty0 = blockIdx.y * 32;
    const int tx0 = blockIdx.x * 32;

    float acc[3][8];
#pragma unroll
    for (int o = 0; o < 3; ++o)
#pragma unroll
        for (int j = 0; j < 8; ++j) acc[o][j] = 0.f;

#pragma unroll 1
    for (int ic0 = 0; ic0 < 64; ic0 += 4) {
        __syncthreads();
        for (int e = tid; e < 4 * 34 * 34; e += 128) {
            int ic = e / 1156;
            int r  = (e % 1156) / 34;
            int c  = e % 34;
            int gy = ty0 - 1 + r;
            int gx = tx0 - 1 + c;
            float v = 0.f;
            if ((unsigned)gy < HH && (unsigned)gx < WW)
                v = __half2float(img[(size_t)(ic0 + ic) * HW + gy * WW + gx]);
            sK[ic][r][c] = v;
        }
        __syncthreads();

#pragma unroll 1
        for (int ic = 0; ic < 4; ++ic) {
#pragma unroll
            for (int ky = 0; ky < 3; ++ky) {
                const float* rp = &sK[ic][row + ky][seg];
                float4 v0 = *(const float4*)rp;
                float4 v1 = *(const float4*)(rp + 4);
                float2 v2 = *(const float2*)(rp + 8);
                float rowv[10] = { v0.x, v0.y, v0.z, v0.w,
                                   v1.x, v1.y, v1.z, v1.w,
                                   v2.x, v2.y };
#pragma unroll
                for (int kx = 0; kx < 3; ++kx) {
                    const int wb = (ic0 + ic) * 9 + ky * 3 + kx;
                    const float w0 = sW2[wb];
                    const float w1 = sW2[576 + wb];
                    const float wv2 = sW2[1152 + wb];
#pragma unroll
                    for (int j = 0; j < 8; ++j) {
                        acc[0][j] = fmaf(w0,  rowv[kx + j], acc[0][j]);
                        acc[1][j] = fmaf(w1,  rowv[kx + j], acc[1][j]);
                        acc[2][j] = fmaf(wv2, rowv[kx + j], acc[2][j]);
                    }
                }
            }
        }
    }

    const int y = ty0 + row;
    if (y < HH) {
        const int offc[6] = {0, 2, 3, 6, 8, 9};
        const int nch[6]  = {2, 1, 3, 2, 1, 3};
        for (int o = 0; o < nch[head]; ++o) {
            const float bias = b2[head * 3 + o];
            float* orow = out + OFF_HEAD +
                ((size_t)b * 12 + offc[head] + o) * HW + (size_t)y * WW;
#pragma unroll
            for (int j = 0; j < 8; ++j) {
                const int x = tx0 + seg + j;
                if (x < WW) orow[x] = acc[o][j] + bias;
            }
        }
    }
}

// -------- tail + target assignment --------
__global__ void zero_tail_kernel(float* __restrict__ out)
{
    const int n = OUT_TOTAL - OFF_HM;
    int i = blockIdx.x * blockDim.x + threadIdx.x;
    if (i < n) out[OFF_HM + i] = 0.f;
}

__global__ void assign_kernel(const float* __restrict__ gt, float* __restrict__ out)
{
    const int t = blockIdx.x * blockDim.x + threadIdx.x;
    if (t >= BB * MM) return;
    const int b = t / MM;
    const int m = t % MM;
    const float* gb = gt + (size_t)(b * MM + m) * 8;

    const float x  = gb[0], y  = gb[1], zc = gb[2];
    const float dx = gb[3], dy = gb[4], dz = gb[5];
    const float hd = gb[6];
    const int   cls = (int)gb[7];

    const bool valid = (dx > 0.f) && (dy > 0.f);
    const float vf = valid ? 1.f : 0.f;

    float cx = (x + 75.2f) / 0.1f / 8.0f;
    cx = fminf(fmaxf(cx, 0.f), (float)WW - 0.5f);
    float cy = (y + 75.2f) / 0.1f / 8.0f;
    cy = fminf(fmaxf(cy, 0.f), (float)HH - 0.5f);
    const int cxi = (int)floorf(cx);
    const int cyi = (int)floorf(cy);

    const float dxp = dx / 0.1f / 8.0f;
    const float dyp = dy / 0.1f / 8.0f;

    const float ov = 0.1f;
    const float hgt = dxp, wdt = dyp;
    const float b1 = hgt + wdt;
    const float c1 = wdt * hgt * (1.f - ov) / (1.f + ov);
    const float sq1 = sqrtf(fmaxf(b1 * b1 - 4.f * c1, 0.f));
    const float r1 = (b1 + sq1) * 0.5f;
    const float b2v = 2.f * (hgt + wdt);
    const float c2 = (1.f - ov) * wdt * hgt;
    const float sq2 = sqrtf(fmaxf(b2v * b2v - 16.f * c2, 0.f));
    const float r2 = (b2v + sq2) * 0.5f;
    const float a3 = 4.f * ov;
    const float b3 = -2.f * ov * (hgt + wdt);
    const float c3 = (ov - 1.f) * wdt * hgt;
    const float sq3 = sqrtf(fmaxf(b3 * b3 - 4.f * a3 * c3, 0.f));
    const float r3 = (b3 + sq3) * 0.5f;

    float r = fminf(fminf(r1, r2), r3);
    r = fmaxf(floorf(r), 2.0f);
    const float sigma = (2.f * r + 1.f) / 6.f;
    const float inv2s2 = 1.f / (2.f * sigma * sigma);

    float* tb = out + OFF_TB + (size_t)(b * NMAX + m) * 8;
    tb[0] = (cx - (float)cxi) * vf;
    tb[1] = (cy - (float)cyi) * vf;
    tb[2] = zc * vf;
    tb[3] = logf(dx) * vf;
    tb[4] = logf(dy) * vf;
    tb[5] = logf(dz) * vf;
    tb[6] = cosf(hd) * vf;
    tb[7] = sinf(hd) * vf;
    out[OFF_IND + b * NMAX + m]  = (float)((cyi * WW + cxi) * (valid ? 1 : 0));
    out[OFF_MASK + b * NMAX + m] = vf;

    if (!valid || cls < 1 || cls > 3) return;

    float* hm = out + OFF_HM + ((size_t)(b * 3 + (cls - 1))) * HW;
    const int ir = (int)r;
    for (int oy = -ir; oy <= ir; ++oy) {
        const int py = cyi + oy;
        if ((unsigned)py >= HH) continue;
        for (int ox = -ir; ox <= ir; ++ox) {
            const int px = cxi + ox;
            if ((unsigned)px >= WW) continue;
            const float g = expf(-(float)(oy * oy + ox * ox) * inv2s2);
            atomicMax((int*)&hm[(size_t)py * WW + px], __float_as_int(g));
        }
    }
}

// ---------------------------------------------------------------------------
extern "C" void kernel_launch(void* const* d_in, const int* in_sizes, int n_in,
                              void* d_out, int out_size)
{
    const float* sf       = (const float*)d_in[0];
    const float* gt       = (const float*)d_in[1];
    const float* w_shared = (const float*)d_in[2];
    const float* bn_sh    = (const float*)d_in[3];
    const float* w1       = (const float*)d_in[4];
    const float* bnh      = (const float*)d_in[5];
    const float* w2       = (const float*)d_in[6];
    const float* b2       = (const float*)d_in[7];
    float* out = (float*)d_out;

    (void)in_sizes; (void)n_in; (void)out_size;

    cudaFuncSetAttribute(mconv2_mh, cudaFuncAttributeMaxDynamicSharedMemorySize, SM2_TOTAL);

    // launch order keeps mconv1 at index 3 for the ncu skip window
    convert_x<<<dim3(7, SLAB_H, BB), 256>>>(sf);
    wtrans0<<<1152, 256>>>(w_shared);
    wtrans1<<<864, 256>>>(w1);

    // stage 1: 512 -> 64 (+BN+ReLU) -> fp16 slab
    mconv1<<<dim3(HH, BB), 256, SM1_TOTAL>>>(bn_sh);
    // stage 2: 64 -> 64 (+BN+ReLU), all 6 heads per CTA -> fp16 NCHW hidden
    mconv2_mh<<<dim3(HH, BB), 256, SM2_TOTAL>>>(bnh);
    // conv2: 64 -> 3 (+bias) with channel-select concat
    conv2_kernel<<<dim3(6, 6, 24), 128>>>(w2, b2, out);

    // independent tail work (zero then splat) after convs
    {
        const int n = OUT_TOTAL - OFF_HM;
        zero_tail_kernel<<<(n + 255) / 256, 256>>>(out);
    }
    assign_kernel<<<(BB * MM + 255) / 256, 256>>>(gt, out);
}